// round 6
// baseline (speedup 1.0000x reference)
#include <cuda_runtime.h>
#include <cuda_bf16.h>

// out[bt, i*16 + j] = x[bt, i] * W[i, j] + b[i, j]
// 256 MB fp32 write stream; measured write ceiling ~5.1 TB/s sustained.
// R6: best-known structure (register-hoisted W/b + .cs stores) with maximum
// per-thread contiguity: each thread owns one (bt, i) -> all 16 outputs ->
// two adjacent st.cs.v8 (64B contiguous per thread, 2KB per warp), one x load
// per 16 outputs, exact-division grid (no tail).

#define C_IN   128
#define C_OUT  16
#define TOTAL_F16 (4194304u)            // 32768 bt * 128 i, one unit = 16 floats

#define NBLOCKS  1024
#define NTHREADS 256
#define STRIDE   (NBLOCKS * NTHREADS)   // 2^18, multiple of 128
#define NITERS   (TOTAL_F16 / STRIDE)   // exactly 16

__global__ __launch_bounds__(NTHREADS, 8)
void real_embedding_kernel(const float* __restrict__ x,
                           const float* __restrict__ W,
                           const float* __restrict__ b,
                           float* __restrict__ out)
{
    const unsigned tid0 = blockIdx.x * NTHREADS + threadIdx.x;

    // STRIDE is a multiple of 128 -> per-thread feature index i is loop-invariant.
    const unsigned i = tid0 & 127u;

    // This thread's full W/b row (16 floats each) in registers.
    const float4* W4 = (const float4*)(W + i * C_OUT);
    const float4* B4 = (const float4*)(b + i * C_OUT);
    const float4 w0 = W4[0], w1 = W4[1], w2 = W4[2], w3 = W4[3];
    const float4 c0 = B4[0], c1 = B4[1], c2 = B4[2], c3 = B4[3];

    const unsigned bt_step = STRIDE >> 7;     // 2048 bt per iteration
    unsigned bt  = tid0 >> 7;
    unsigned gid = tid0;

#pragma unroll 1
    for (unsigned o = 0; o < NITERS; o++) {
        const float xv = __ldg(x + (size_t)bt * C_IN + i);

        const float r0 = fmaf(xv, w0.x, c0.x), r1 = fmaf(xv, w0.y, c0.y);
        const float r2 = fmaf(xv, w0.z, c0.z), r3 = fmaf(xv, w0.w, c0.w);
        const float r4 = fmaf(xv, w1.x, c1.x), r5 = fmaf(xv, w1.y, c1.y);
        const float r6 = fmaf(xv, w1.z, c1.z), r7 = fmaf(xv, w1.w, c1.w);
        const float r8 = fmaf(xv, w2.x, c2.x), r9 = fmaf(xv, w2.y, c2.y);
        const float rA = fmaf(xv, w2.z, c2.z), rB = fmaf(xv, w2.w, c2.w);
        const float rC = fmaf(xv, w3.x, c3.x), rD = fmaf(xv, w3.y, c3.y);
        const float rE = fmaf(xv, w3.z, c3.z), rF = fmaf(xv, w3.w, c3.w);

        float* dst = out + (size_t)gid * 16;   // 64B-aligned, contiguous pair
        asm volatile("st.global.cs.v8.f32 [%0], {%1,%2,%3,%4,%5,%6,%7,%8};" ::
            "l"(dst),
            "f"(r0),"f"(r1),"f"(r2),"f"(r3),
            "f"(r4),"f"(r5),"f"(r6),"f"(r7) : "memory");
        asm volatile("st.global.cs.v8.f32 [%0], {%1,%2,%3,%4,%5,%6,%7,%8};" ::
            "l"(dst + 8),
            "f"(r8),"f"(r9),"f"(rA),"f"(rB),
            "f"(rC),"f"(rD),"f"(rE),"f"(rF) : "memory");

        gid += STRIDE;
        bt  += bt_step;
    }
}

extern "C" void kernel_launch(void* const* d_in, const int* in_sizes, int n_in,
                              void* d_out, int out_size) {
    const float* x = (const float*)d_in[0];
    const float* W = (const float*)d_in[1];
    const float* b = (const float*)d_in[2];
    float* out = (float*)d_out;

    (void)in_sizes; (void)n_in; (void)out_size;

    real_embedding_kernel<<<NBLOCKS, NTHREADS>>>(x, W, b, out);
}

// round 7
// speedup vs baseline: 1.0031x; 1.0031x over previous
#include <cuda_runtime.h>
#include <cuda_bf16.h>

// out[bt, i*16 + j] = x[bt, i] * W[i, j] + b[i, j]
// 256 MB fp32 write stream. R5/R6 regressions were grid-imbalance artifacts
// (1024 blocks on 148 SMs -> 7-vs-6 blocks/SM). R7: R3 structure (reg-hoisted
// W/b, dense warp stores, .cs) + 4-deep independent load/store batching +
// balanced grid (148*8 = 1184 blocks).

#define C_IN   128
#define C_OUT  16
#define TOTAL_F8 8388608u               // 2^23 float8 units

#define NBLOCKS  (148 * 8)
#define NTHREADS 256
#define STRIDE   ((unsigned)NBLOCKS * NTHREADS)   // 303,104 (multiple of 256)

__global__ __launch_bounds__(NTHREADS, 8)
void real_embedding_kernel(const float* __restrict__ x,
                           const float* __restrict__ W,
                           const float* __restrict__ b,
                           float* __restrict__ out)
{
    const unsigned tid0 = blockIdx.x * NTHREADS + threadIdx.x;

    // STRIDE multiple of 256 -> per-thread (i, h) loop-invariant.
    const unsigned h = tid0 & 1u;
    const unsigned i = (tid0 >> 1) & 127u;

    const float4* W4 = (const float4*)(W + i * C_OUT + h * 8);
    const float4* B4 = (const float4*)(b + i * C_OUT + h * 8);
    const float4 w0 = W4[0], w1 = W4[1];
    const float4 c0 = B4[0], c1 = B4[1];

    const unsigned bt_step = STRIDE >> 8;
    unsigned gid = tid0;
    unsigned bt  = tid0 >> 8;

    // 4-deep batched main loop: 4 independent LDG -> 32 FMA -> 4 dense v8 stores.
    while (gid + 3u * STRIDE < TOTAL_F8) {
        const float xv0 = __ldg(x + (size_t)(bt)               * C_IN + i);
        const float xv1 = __ldg(x + (size_t)(bt +     bt_step) * C_IN + i);
        const float xv2 = __ldg(x + (size_t)(bt + 2 * bt_step) * C_IN + i);
        const float xv3 = __ldg(x + (size_t)(bt + 3 * bt_step) * C_IN + i);

        float r0[8], r1[8], r2[8], r3[8];
        r0[0]=fmaf(xv0,w0.x,c0.x); r0[1]=fmaf(xv0,w0.y,c0.y); r0[2]=fmaf(xv0,w0.z,c0.z); r0[3]=fmaf(xv0,w0.w,c0.w);
        r0[4]=fmaf(xv0,w1.x,c1.x); r0[5]=fmaf(xv0,w1.y,c1.y); r0[6]=fmaf(xv0,w1.z,c1.z); r0[7]=fmaf(xv0,w1.w,c1.w);
        r1[0]=fmaf(xv1,w0.x,c0.x); r1[1]=fmaf(xv1,w0.y,c0.y); r1[2]=fmaf(xv1,w0.z,c0.z); r1[3]=fmaf(xv1,w0.w,c0.w);
        r1[4]=fmaf(xv1,w1.x,c1.x); r1[5]=fmaf(xv1,w1.y,c1.y); r1[6]=fmaf(xv1,w1.z,c1.z); r1[7]=fmaf(xv1,w1.w,c1.w);
        r2[0]=fmaf(xv2,w0.x,c0.x); r2[1]=fmaf(xv2,w0.y,c0.y); r2[2]=fmaf(xv2,w0.z,c0.z); r2[3]=fmaf(xv2,w0.w,c0.w);
        r2[4]=fmaf(xv2,w1.x,c1.x); r2[5]=fmaf(xv2,w1.y,c1.y); r2[6]=fmaf(xv2,w1.z,c1.z); r2[7]=fmaf(xv2,w1.w,c1.w);
        r3[0]=fmaf(xv3,w0.x,c0.x); r3[1]=fmaf(xv3,w0.y,c0.y); r3[2]=fmaf(xv3,w0.z,c0.z); r3[3]=fmaf(xv3,w0.w,c0.w);
        r3[4]=fmaf(xv3,w1.x,c1.x); r3[5]=fmaf(xv3,w1.y,c1.y); r3[6]=fmaf(xv3,w1.z,c1.z); r3[7]=fmaf(xv3,w1.w,c1.w);

        float* d0 = out + (size_t)(gid)              * 8;
        float* d1 = out + (size_t)(gid +     STRIDE) * 8;
        float* d2 = out + (size_t)(gid + 2 * STRIDE) * 8;
        float* d3 = out + (size_t)(gid + 3 * STRIDE) * 8;
        asm volatile("st.global.cs.v8.f32 [%0], {%1,%2,%3,%4,%5,%6,%7,%8};" ::
            "l"(d0), "f"(r0[0]),"f"(r0[1]),"f"(r0[2]),"f"(r0[3]),
                     "f"(r0[4]),"f"(r0[5]),"f"(r0[6]),"f"(r0[7]) : "memory");
        asm volatile("st.global.cs.v8.f32 [%0], {%1,%2,%3,%4,%5,%6,%7,%8};" ::
            "l"(d1), "f"(r1[0]),"f"(r1[1]),"f"(r1[2]),"f"(r1[3]),
                     "f"(r1[4]),"f"(r1[5]),"f"(r1[6]),"f"(r1[7]) : "memory");
        asm volatile("st.global.cs.v8.f32 [%0], {%1,%2,%3,%4,%5,%6,%7,%8};" ::
            "l"(d2), "f"(r2[0]),"f"(r2[1]),"f"(r2[2]),"f"(r2[3]),
                     "f"(r2[4]),"f"(r2[5]),"f"(r2[6]),"f"(r2[7]) : "memory");
        asm volatile("st.global.cs.v8.f32 [%0], {%1,%2,%3,%4,%5,%6,%7,%8};" ::
            "l"(d3), "f"(r3[0]),"f"(r3[1]),"f"(r3[2]),"f"(r3[3]),
                     "f"(r3[4]),"f"(r3[5]),"f"(r3[6]),"f"(r3[7]) : "memory");

        gid += 4u * STRIDE;
        bt  += 4u * bt_step;
    }

    // Tail (<= 3 iterations per thread).
    while (gid < TOTAL_F8) {
        const float xv = __ldg(x + (size_t)bt * C_IN + i);
        const float r0 = fmaf(xv, w0.x, c0.x), r1 = fmaf(xv, w0.y, c0.y);
        const float r2 = fmaf(xv, w0.z, c0.z), r3 = fmaf(xv, w0.w, c0.w);
        const float r4 = fmaf(xv, w1.x, c1.x), r5 = fmaf(xv, w1.y, c1.y);
        const float r6 = fmaf(xv, w1.z, c1.z), r7 = fmaf(xv, w1.w, c1.w);
        float* dst = out + (size_t)gid * 8;
        asm volatile("st.global.cs.v8.f32 [%0], {%1,%2,%3,%4,%5,%6,%7,%8};" ::
            "l"(dst), "f"(r0),"f"(r1),"f"(r2),"f"(r3),
                      "f"(r4),"f"(r5),"f"(r6),"f"(r7) : "memory");
        gid += STRIDE;
        bt  += bt_step;
    }
}

extern "C" void kernel_launch(void* const* d_in, const int* in_sizes, int n_in,
                              void* d_out, int out_size) {
    const float* x = (const float*)d_in[0];
    const float* W = (const float*)d_in[1];
    const float* b = (const float*)d_in[2];
    float* out = (float*)d_out;

    (void)in_sizes; (void)n_in; (void)out_size;

    real_embedding_kernel<<<NBLOCKS, NTHREADS>>>(x, W, b, out);
}

// round 8
// speedup vs baseline: 1.1131x; 1.1096x over previous
#include <cuda_runtime.h>
#include <cuda_bf16.h>

// out[bt, i*16 + j] = x[bt, i] * W[i, j] + b[i, j]
// 256 MB fp32 write stream + 16 MB x read. R1-R7: all SM-side store-path
// variants pin at ~4.4-4.5 TB/s; dense single-store loop (R3) is best.
// R8 theory: DRAM read/write turnaround. Front-load ALL of x into L2 with a
// one-shot prefetch burst so the main loop is a near-pure write stream.

#define C_IN   128
#define C_OUT  16
#define TOTAL_F8 8388608u               // 2^23 float8 units
#define X_LINES  131072u                // 16 MB / 128B

#define NBLOCKS  (148 * 8)
#define NTHREADS 256
#define STRIDE   ((unsigned)NBLOCKS * NTHREADS)   // 303,104 (multiple of 256)

__global__ __launch_bounds__(NTHREADS, 8)
void real_embedding_kernel(const float* __restrict__ x,
                           const float* __restrict__ W,
                           const float* __restrict__ b,
                           float* __restrict__ out)
{
    const unsigned tid0 = blockIdx.x * NTHREADS + threadIdx.x;

    // One-shot L2 prefetch of the entire x tensor (one 128B line per thread
    // for the first 131072 threads). Fire-and-forget; later demand loads
    // either hit L2 or merge with the in-flight miss.
    if (tid0 < X_LINES) {
        const float* p = x + (size_t)tid0 * 32;   // 32 floats = 128B line
        asm volatile("prefetch.global.L2 [%0];" :: "l"(p));
    }

    // STRIDE multiple of 256 -> per-thread (i, h) loop-invariant.
    const unsigned h = tid0 & 1u;
    const unsigned i = (tid0 >> 1) & 127u;

    const float4* W4 = (const float4*)(W + i * C_OUT + h * 8);
    const float4* B4 = (const float4*)(b + i * C_OUT + h * 8);
    const float4 w0 = W4[0], w1 = W4[1];
    const float4 c0 = B4[0], c1 = B4[1];

    const unsigned bt_step = STRIDE >> 8;
    unsigned bt = tid0 >> 8;

#pragma unroll 1
    for (unsigned gid = tid0; gid < TOTAL_F8; gid += STRIDE, bt += bt_step) {
        const float xv = __ldg(x + (size_t)bt * C_IN + i);

        const float r0 = fmaf(xv, w0.x, c0.x), r1 = fmaf(xv, w0.y, c0.y);
        const float r2 = fmaf(xv, w0.z, c0.z), r3 = fmaf(xv, w0.w, c0.w);
        const float r4 = fmaf(xv, w1.x, c1.x), r5 = fmaf(xv, w1.y, c1.y);
        const float r6 = fmaf(xv, w1.z, c1.z), r7 = fmaf(xv, w1.w, c1.w);

        float* dst = out + (size_t)gid * 8;   // 32B-aligned, warp-dense 1KB
        asm volatile("st.global.cs.v8.f32 [%0], {%1,%2,%3,%4,%5,%6,%7,%8};" ::
            "l"(dst), "f"(r0),"f"(r1),"f"(r2),"f"(r3),
                      "f"(r4),"f"(r5),"f"(r6),"f"(r7) : "memory");
    }
}

extern "C" void kernel_launch(void* const* d_in, const int* in_sizes, int n_in,
                              void* d_out, int out_size) {
    const float* x = (const float*)d_in[0];
    const float* W = (const float*)d_in[1];
    const float* b = (const float*)d_in[2];
    float* out = (float*)d_out;

    (void)in_sizes; (void)n_in; (void)out_size;

    real_embedding_kernel<<<NBLOCKS, NTHREADS>>>(x, W, b, out);
}

// round 9
// speedup vs baseline: 1.1190x; 1.0052x over previous
#include <cuda_runtime.h>
#include <cuda_bf16.h>

// out[bt, i*16 + j] = x[bt, i] * W[i, j] + b[i, j]
// 256 MB fp32 write stream + 16 MB x read. R1-R7: all SM-side store-path
// variants pin at ~4.4-4.5 TB/s; dense single-store loop (R3) is best.
// R8 theory: DRAM read/write turnaround. Front-load ALL of x into L2 with a
// one-shot prefetch burst so the main loop is a near-pure write stream.

#define C_IN   128
#define C_OUT  16
#define TOTAL_F8 8388608u               // 2^23 float8 units
#define X_LINES  131072u                // 16 MB / 128B

#define NBLOCKS  (148 * 8)
#define NTHREADS 256
#define STRIDE   ((unsigned)NBLOCKS * NTHREADS)   // 303,104 (multiple of 256)

__global__ __launch_bounds__(NTHREADS, 8)
void real_embedding_kernel(const float* __restrict__ x,
                           const float* __restrict__ W,
                           const float* __restrict__ b,
                           float* __restrict__ out)
{
    const unsigned tid0 = blockIdx.x * NTHREADS + threadIdx.x;

    // One-shot L2 prefetch of the entire x tensor (one 128B line per thread
    // for the first 131072 threads). Fire-and-forget; later demand loads
    // either hit L2 or merge with the in-flight miss.
    if (tid0 < X_LINES) {
        const float* p = x + (size_t)tid0 * 32;   // 32 floats = 128B line
        asm volatile("prefetch.global.L2 [%0];" :: "l"(p));
    }

    // STRIDE multiple of 256 -> per-thread (i, h) loop-invariant.
    const unsigned h = tid0 & 1u;
    const unsigned i = (tid0 >> 1) & 127u;

    const float4* W4 = (const float4*)(W + i * C_OUT + h * 8);
    const float4* B4 = (const float4*)(b + i * C_OUT + h * 8);
    const float4 w0 = W4[0], w1 = W4[1];
    const float4 c0 = B4[0], c1 = B4[1];

    const unsigned bt_step = STRIDE >> 8;
    unsigned bt = tid0 >> 8;

#pragma unroll 1
    for (unsigned gid = tid0; gid < TOTAL_F8; gid += STRIDE, bt += bt_step) {
        const float xv = __ldg(x + (size_t)bt * C_IN + i);

        const float r0 = fmaf(xv, w0.x, c0.x), r1 = fmaf(xv, w0.y, c0.y);
        const float r2 = fmaf(xv, w0.z, c0.z), r3 = fmaf(xv, w0.w, c0.w);
        const float r4 = fmaf(xv, w1.x, c1.x), r5 = fmaf(xv, w1.y, c1.y);
        const float r6 = fmaf(xv, w1.z, c1.z), r7 = fmaf(xv, w1.w, c1.w);

        float* dst = out + (size_t)gid * 8;   // 32B-aligned, warp-dense 1KB
        asm volatile("st.global.cs.v8.f32 [%0], {%1,%2,%3,%4,%5,%6,%7,%8};" ::
            "l"(dst), "f"(r0),"f"(r1),"f"(r2),"f"(r3),
                      "f"(r4),"f"(r5),"f"(r6),"f"(r7) : "memory");
    }
}

extern "C" void kernel_launch(void* const* d_in, const int* in_sizes, int n_in,
                              void* d_out, int out_size) {
    const float* x = (const float*)d_in[0];
    const float* W = (const float*)d_in[1];
    const float* b = (const float*)d_in[2];
    float* out = (float*)d_out;

    (void)in_sizes; (void)n_in; (void)out_size;

    real_embedding_kernel<<<NBLOCKS, NTHREADS>>>(x, W, b, out);
}